// round 5
// baseline (speedup 1.0000x reference)
#include <cuda_runtime.h>
#include <cuda_bf16.h>
#include <math.h>

// Problem constants (fixed by the dataset)
#define NMAX 100000
#define EMAX 1600000
#define F    128
#define G    64
#define OUTD 10

// ---------------- device scratch (static, no allocation) ----------------
__device__ float g_bufA[(size_t)NMAX * F];   // GEMM output h = x @ W
__device__ float g_bufB[(size_t)NMAX * F];   // aggregation output / next layer input
__device__ float g_dinv[NMAX];
__device__ int   g_deg[NMAX];
__device__ float g_norm[EMAX];
__device__ int   g_src[EMAX];
__device__ int   g_dst[EMAX];
__device__ float g_gsum[G * F];
__device__ int   g_gcnt[G];

// ---------------- helpers ----------------
__device__ __forceinline__ void red_add_v4(float* addr, float x, float y, float z, float w) {
    asm volatile("red.global.add.v4.f32 [%0], {%1,%2,%3,%4};"
                 :: "l"(addr), "f"(x), "f"(y), "f"(z), "f"(w) : "memory");
}

__device__ __forceinline__ int clampi(int v, int lo, int hi) {
    return v < lo ? lo : (v > hi ? hi : v);
}

// ---------------- degree / norm precompute ----------------
__global__ void k_deg_init(int n) {
    int i = blockIdx.x * blockDim.x + threadIdx.x;
    if (i < n) g_deg[i] = 1;            // self loop contributes 1
}

__global__ void k_deg_count(const int* __restrict__ dst, int e, int n) {
    int i = blockIdx.x * blockDim.x + threadIdx.x;
    if (i < e) atomicAdd(&g_deg[clampi(dst[i], 0, n - 1)], 1);
}

__global__ void k_dinv(int n) {
    int i = blockIdx.x * blockDim.x + threadIdx.x;
    if (i < n) g_dinv[i] = rsqrtf((float)g_deg[i]);
}

__global__ void k_norm(const int* __restrict__ src, const int* __restrict__ dst, int e, int n) {
    int i = blockIdx.x * blockDim.x + threadIdx.x;
    if (i < e) {
        int s = clampi(src[i], 0, n - 1);
        int d = clampi(dst[i], 0, n - 1);
        g_src[i] = s;
        g_dst[i] = d;
        g_norm[i] = g_dinv[s] * g_dinv[d];
    }
}

// ---------------- GEMM: g_bufA[n x 128] = X[n x 128] @ W[128 x 128] ------------
// X = external input (use_ext=1) or g_bufB (use_ext=0).
// Block: 256 threads, 64 rows x 128 cols tile; per-thread 4x8; k-tiles of 32.
__global__ void k_gemm128(const float* __restrict__ Xext, int use_ext,
                          const float* __restrict__ W, int nrows)
{
    const float* X = use_ext ? Xext : (const float*)g_bufB;
    float*       Y = g_bufA;

    __shared__ __align__(16) float sW[32 * 128];  // W[kt..kt+31][0..127]
    __shared__ __align__(16) float sXT[32 * 65];  // X transposed tile: [k][row], pad 65

    int tid  = threadIdx.x;
    int row0 = blockIdx.x * 64;
    int tc   = (tid & 15) * 8;           // col base (0..120)
    int tr   = (tid >> 4) * 4;           // row base (0..60)

    float acc[4][8];
#pragma unroll
    for (int i = 0; i < 4; i++)
#pragma unroll
        for (int j = 0; j < 8; j++) acc[i][j] = 0.f;

    for (int kt = 0; kt < 128; kt += 32) {
        // load W tile: 32x128 floats = 1024 float4, 4 per thread
        {
            const float4* W4  = (const float4*)(W + kt * 128);
            float4*       sW4 = (float4*)sW;
#pragma unroll
            for (int i = 0; i < 4; i++) sW4[tid + 256 * i] = W4[tid + 256 * i];
        }
        // load X tile transposed: rows row0..row0+63, cols kt..kt+31
        {
#pragma unroll
            for (int i = 0; i < 2; i++) {
                int li = tid + 256 * i;          // 0..511
                int r  = li >> 3;                // 0..63
                int c  = (li & 7) * 4;           // 0,4,..28
                float4 v = make_float4(0.f, 0.f, 0.f, 0.f);
                if (row0 + r < nrows)
                    v = *(const float4*)(X + (size_t)(row0 + r) * 128 + kt + c);
                sXT[(c + 0) * 65 + r] = v.x;
                sXT[(c + 1) * 65 + r] = v.y;
                sXT[(c + 2) * 65 + r] = v.z;
                sXT[(c + 3) * 65 + r] = v.w;
            }
        }
        __syncthreads();

#pragma unroll
        for (int k = 0; k < 32; k++) {
            float4 w0 = *(const float4*)&sW[k * 128 + tc];
            float4 w1 = *(const float4*)&sW[k * 128 + tc + 4];
            float a0 = sXT[k * 65 + tr + 0];
            float a1 = sXT[k * 65 + tr + 1];
            float a2 = sXT[k * 65 + tr + 2];
            float a3 = sXT[k * 65 + tr + 3];
            float wv[8] = {w0.x, w0.y, w0.z, w0.w, w1.x, w1.y, w1.z, w1.w};
#pragma unroll
            for (int j = 0; j < 8; j++) {
                acc[0][j] = fmaf(a0, wv[j], acc[0][j]);
                acc[1][j] = fmaf(a1, wv[j], acc[1][j]);
                acc[2][j] = fmaf(a2, wv[j], acc[2][j]);
                acc[3][j] = fmaf(a3, wv[j], acc[3][j]);
            }
        }
        __syncthreads();
    }

#pragma unroll
    for (int r = 0; r < 4; r++) {
        int row = row0 + tr + r;
        if (row < nrows) {
            float4* o = (float4*)(Y + (size_t)row * 128 + tc);
            o[0] = make_float4(acc[r][0], acc[r][1], acc[r][2], acc[r][3]);
            o[1] = make_float4(acc[r][4], acc[r][5], acc[r][6], acc[r][7]);
        }
    }
}

// ---------------- self-loop init: g_bufB = dinv^2 * g_bufA ----------------
__global__ void k_selfinit(int n) {
    int idx = blockIdx.x * blockDim.x + threadIdx.x;    // n*32 float4 units
    if (idx >= n * 32) return;
    int node = idx >> 5;
    float dv = g_dinv[node];
    float s  = dv * dv;
    float4 v = ((const float4*)g_bufA)[idx];
    v.x *= s; v.y *= s; v.z *= s; v.w *= s;
    ((float4*)g_bufB)[idx] = v;
}

// ------- edge scatter: g_bufB[dst] += norm * g_bufA[src]  (warp per edge) ------
__global__ void k_scatter(int e) {
    int gt   = blockIdx.x * blockDim.x + threadIdx.x;
    int w    = gt >> 5;
    int lane = gt & 31;
    if (w >= e) return;
    int   s  = g_src[w];
    int   d  = g_dst[w];
    float nv = g_norm[w];
    float4 v = *(const float4*)((const float*)g_bufA + (size_t)s * 128 + lane * 4);
    float* o = (float*)g_bufB + (size_t)d * 128 + lane * 4;
    red_add_v4(o, nv * v.x, nv * v.y, nv * v.z, nv * v.w);
}

// ---------------- bias + optional PReLU (in place on g_bufB) ----------------
__global__ void k_finalize(const float* __restrict__ bias,
                           const float* __restrict__ a, int n, int do_prelu) {
    int idx = blockIdx.x * blockDim.x + threadIdx.x;    // n*32 float4 units
    if (idx >= n * 32) return;
    int f = (idx & 31) * 4;
    float4 v = ((float4*)g_bufB)[idx];
    v.x += bias[f + 0];
    v.y += bias[f + 1];
    v.z += bias[f + 2];
    v.w += bias[f + 3];
    if (do_prelu) {
        float alpha = a[0];
        v.x = v.x > 0.f ? v.x : alpha * v.x;
        v.y = v.y > 0.f ? v.y : alpha * v.y;
        v.z = v.z > 0.f ? v.z : alpha * v.z;
        v.w = v.w > 0.f ? v.w : alpha * v.w;
    }
    ((float4*)g_bufB)[idx] = v;
}

// ---------------- pooling ----------------
__global__ void k_pool_init(const int* __restrict__ batch, int n) {
    int t = threadIdx.x;                       // 1 block, 128 threads
    for (int i = t; i < G * F; i += blockDim.x) g_gsum[i] = 0.f;
    if (t < G) {
        // lower_bound(batch, t) and lower_bound(batch, t+1) — batch is sorted
        int lo, hi;
        {
            int a = 0, b = n;
            while (a < b) { int m = (a + b) >> 1; if (batch[m] < t) a = m + 1; else b = m; }
            lo = a;
        }
        {
            int a = 0, b = n;
            while (a < b) { int m = (a + b) >> 1; if (batch[m] < t + 1) a = m + 1; else b = m; }
            hi = a;
        }
        g_gcnt[t] = hi - lo;
    }
}

// 128 threads per block (one per feature); each block handles 256 nodes.
__global__ void k_pool_sum(const int* __restrict__ batch, int n) {
    int f  = threadIdx.x;                      // 0..127
    int n0 = blockIdx.x * 256;
    int n1 = min(n0 + 256, n);
    int gc = -1;
    float acc = 0.f;
    const float* H = g_bufB;
    for (int nn = n0; nn < n1; nn++) {
        int g = clampi(batch[nn], 0, G - 1);
        if (g != gc) {
            if (gc >= 0) atomicAdd(&g_gsum[gc * F + f], acc);
            acc = 0.f;
            gc = g;
        }
        acc += H[(size_t)nn * F + f];
    }
    if (gc >= 0) atomicAdd(&g_gsum[gc * F + f], acc);
}

__global__ void k_head(const float* __restrict__ linW, const float* __restrict__ linb,
                       float* __restrict__ out) {
    int t = blockIdx.x * blockDim.x + threadIdx.x;     // 640 outputs
    if (t >= G * OUTD) return;
    int g = t / OUTD;
    int o = t % OUTD;
    float c   = fmaxf((float)g_gcnt[g], 1.f);
    float inv = 1.f / c;
    float acc = 0.f;
#pragma unroll 8
    for (int h = 0; h < F; h++)
        acc = fmaf(g_gsum[g * F + h], linW[h * OUTD + o], acc);
    out[t] = acc * inv + linb[o];
}

// ---------------- launch ----------------
extern "C" void kernel_launch(void* const* d_in, const int* in_sizes, int n_in,
                              void* d_out, int out_size)
{
    // Resolve inputs BY SIZE (robust to metadata ordering). Same-shaped tensors
    // (W0/W1/W2, b0/b1/b2, a0/a1) keep their relative order.
    int iX = 0, iE = 0, iB = 0, iLW = 0, iLb = 0;
    int iW[3] = {0, 0, 0}, ib[3] = {0, 0, 0}, ia[2] = {0, 0};
    int nW = 0, nb = 0, na = 0;
    for (int i = 0; i < n_in; i++) {
        int s = in_sizes[i];
        if      (s == NMAX * F)   iX = i;              // 12,800,000
        else if (s == 2 * EMAX)   iE = i;              //  3,200,000
        else if (s == NMAX)       iB = i;              //    100,000
        else if (s == F * F)      { if (nW < 3) iW[nW++] = i; }   // 16,384
        else if (s == F)          { if (nb < 3) ib[nb++] = i; }   //    128
        else if (s == 1)          { if (na < 2) ia[na++] = i; }   //      1
        else if (s == F * OUTD)   iLW = i;             //      1,280
        else if (s == OUTD)       iLb = i;             //         10
    }

    const float* x    = (const float*)d_in[iX];
    const int*   ei   = (const int*)d_in[iE];    // int32 (JAX x64 disabled)
    const int*   bat  = (const int*)d_in[iB];    // int32
    const float* W0   = (const float*)d_in[iW[0]];
    const float* b0   = (const float*)d_in[ib[0]];
    const float* a0   = (const float*)d_in[ia[0]];
    const float* W1   = (const float*)d_in[iW[1]];
    const float* b1   = (const float*)d_in[ib[1]];
    const float* a1   = (const float*)d_in[ia[1]];
    const float* W2   = (const float*)d_in[iW[2]];
    const float* b2   = (const float*)d_in[ib[2]];
    const float* linW = (const float*)d_in[iLW];
    const float* linb = (const float*)d_in[iLb];
    float*       out  = (float*)d_out;

    int n = in_sizes[iX] / F;       // 100000
    int e = in_sizes[iE] / 2;       // 1600000
    const int* src = ei;
    const int* dst = ei + e;

    // ---- norm precompute ----
    k_deg_init<<<(n + 255) / 256, 256>>>(n);
    k_deg_count<<<(e + 255) / 256, 256>>>(dst, e, n);
    k_dinv<<<(n + 255) / 256, 256>>>(n);
    k_norm<<<(e + 255) / 256, 256>>>(src, dst, e, n);

    int gemm_blocks = (n + 63) / 64;
    int nf4   = n * 32;                       // float4 units over node features
    int nfb   = (nf4 + 255) / 256;
    long long sc_t = (long long)e * 32;       // warp per edge
    int sc_b  = (int)((sc_t + 255) / 256);

    // ---- layer 1 ----
    k_gemm128<<<gemm_blocks, 256>>>(x, 1, W0, n);
    k_selfinit<<<nfb, 256>>>(n);
    k_scatter<<<sc_b, 256>>>(e);
    k_finalize<<<nfb, 256>>>(b0, a0, n, 1);

    // ---- layer 2 ----
    k_gemm128<<<gemm_blocks, 256>>>(nullptr, 0, W1, n);
    k_selfinit<<<nfb, 256>>>(n);
    k_scatter<<<sc_b, 256>>>(e);
    k_finalize<<<nfb, 256>>>(b1, a1, n, 1);

    // ---- layer 3 (no PReLU) ----
    k_gemm128<<<gemm_blocks, 256>>>(nullptr, 0, W2, n);
    k_selfinit<<<nfb, 256>>>(n);
    k_scatter<<<sc_b, 256>>>(e);
    k_finalize<<<nfb, 256>>>(b2, nullptr, n, 0);

    // ---- pool + head ----
    k_pool_init<<<1, 128>>>(bat, n);
    k_pool_sum<<<(n + 255) / 256, 128>>>(bat, n);
    k_head<<<3, 256>>>(linW, linb, out);
}

// round 6
// speedup vs baseline: 1.4361x; 1.4361x over previous
#include <cuda_runtime.h>
#include <cuda_bf16.h>
#include <math.h>

// Problem constants (fixed by the dataset)
#define NMAX 100000
#define EMAX 1600000
#define F    128
#define G    64
#define OUTD 10

// ---------------- device scratch (static, no allocation) ----------------
__device__ float  g_bufA[(size_t)NMAX * F];  // GEMM output h = x @ W
__device__ float  g_bufB[(size_t)NMAX * F];  // aggregation output / next layer input
__device__ float  g_dinv[NMAX];
__device__ int    g_deg[NMAX];               // degree incl. self loop
__device__ int    g_scan[NMAX];              // per-block inclusive scan of (deg-1)
__device__ int    g_bsum[128];               // block sums -> exclusive offsets
__device__ int    g_rowstart[NMAX];          // CSR row start (real edges only)
__device__ int    g_pos[NMAX];               // fill cursor
__device__ float2 g_edge[EMAX];              // packed (src as int bits, norm)
__device__ float  g_gsum[G * F];
__device__ int    g_gcnt[G];

__device__ __forceinline__ int clampi(int v, int lo, int hi) {
    return v < lo ? lo : (v > hi ? hi : v);
}

// ---------------- degree / dinv ----------------
__global__ void k_deg_init(int n) {
    int i = blockIdx.x * blockDim.x + threadIdx.x;
    if (i < n) g_deg[i] = 1;            // self loop contributes 1
}

__global__ void k_deg_count(const int* __restrict__ dst, int e, int n) {
    int i = blockIdx.x * blockDim.x + threadIdx.x;
    if (i < e) atomicAdd(&g_deg[clampi(dst[i], 0, n - 1)], 1);
}

__global__ void k_dinv(int n) {
    int i = blockIdx.x * blockDim.x + threadIdx.x;
    if (i < n) g_dinv[i] = rsqrtf((float)g_deg[i]);
}

// ---------------- CSR build: scan of (deg-1), then slot fill ----------------
__global__ void k_scan1(int n) {                 // 1024 threads/block
    __shared__ int sh[1024];
    int gid = blockIdx.x * 1024 + threadIdx.x;
    int v = (gid < n) ? (g_deg[gid] - 1) : 0;
    sh[threadIdx.x] = v;
    __syncthreads();
    for (int off = 1; off < 1024; off <<= 1) {   // Hillis-Steele inclusive
        int t = (threadIdx.x >= off) ? sh[threadIdx.x - off] : 0;
        __syncthreads();
        sh[threadIdx.x] += t;
        __syncthreads();
    }
    if (gid < n) g_scan[gid] = sh[threadIdx.x];
    if (threadIdx.x == 1023) g_bsum[blockIdx.x] = sh[1023];
}

__global__ void k_scan2(int nb) {                // 1 block, 128 threads
    __shared__ int sh[128];
    int t = threadIdx.x;
    sh[t] = (t < nb) ? g_bsum[t] : 0;
    __syncthreads();
    if (t == 0) {
        int acc = 0;
        for (int i = 0; i < nb; i++) { int v = sh[i]; sh[i] = acc; acc += v; }
    }
    __syncthreads();
    if (t < nb) g_bsum[t] = sh[t];
}

__global__ void k_scan3(int n) {
    int gid = blockIdx.x * blockDim.x + threadIdx.x;
    if (gid >= n) return;
    int cnt   = g_deg[gid] - 1;
    int start = g_scan[gid] - cnt + g_bsum[gid >> 10];   // exclusive start
    g_rowstart[gid] = start;
    g_pos[gid]      = start;
}

__global__ void k_csr_fill(const int* __restrict__ src, const int* __restrict__ dst,
                           int e, int n) {
    int i = blockIdx.x * blockDim.x + threadIdx.x;
    if (i >= e) return;
    int s = clampi(src[i], 0, n - 1);
    int d = clampi(dst[i], 0, n - 1);
    int slot = atomicAdd(&g_pos[d], 1);
    g_edge[slot] = make_float2(__int_as_float(s), g_dinv[s] * g_dinv[d]);
}

// ---------------- GEMM: g_bufA[n x 128] = X[n x 128] @ W[128 x 128] ------------
// Block: 256 threads, 64 rows x 128 cols tile; per-thread 4x8; k-tiles of 32.
__global__ void k_gemm128(const float* __restrict__ Xext, int use_ext,
                          const float* __restrict__ W, int nrows)
{
    const float* X = use_ext ? Xext : (const float*)g_bufB;
    float*       Y = g_bufA;

    __shared__ __align__(16) float sW[32 * 128];
    __shared__ __align__(16) float sXT[32 * 65];

    int tid  = threadIdx.x;
    int row0 = blockIdx.x * 64;
    int tc   = (tid & 15) * 8;
    int tr   = (tid >> 4) * 4;

    float acc[4][8];
#pragma unroll
    for (int i = 0; i < 4; i++)
#pragma unroll
        for (int j = 0; j < 8; j++) acc[i][j] = 0.f;

    for (int kt = 0; kt < 128; kt += 32) {
        {
            const float4* W4  = (const float4*)(W + kt * 128);
            float4*       sW4 = (float4*)sW;
#pragma unroll
            for (int i = 0; i < 4; i++) sW4[tid + 256 * i] = W4[tid + 256 * i];
        }
        {
#pragma unroll
            for (int i = 0; i < 2; i++) {
                int li = tid + 256 * i;
                int r  = li >> 3;
                int c  = (li & 7) * 4;
                float4 v = make_float4(0.f, 0.f, 0.f, 0.f);
                if (row0 + r < nrows)
                    v = *(const float4*)(X + (size_t)(row0 + r) * 128 + kt + c);
                sXT[(c + 0) * 65 + r] = v.x;
                sXT[(c + 1) * 65 + r] = v.y;
                sXT[(c + 2) * 65 + r] = v.z;
                sXT[(c + 3) * 65 + r] = v.w;
            }
        }
        __syncthreads();

#pragma unroll
        for (int k = 0; k < 32; k++) {
            float4 w0 = *(const float4*)&sW[k * 128 + tc];
            float4 w1 = *(const float4*)&sW[k * 128 + tc + 4];
            float a0 = sXT[k * 65 + tr + 0];
            float a1 = sXT[k * 65 + tr + 1];
            float a2 = sXT[k * 65 + tr + 2];
            float a3 = sXT[k * 65 + tr + 3];
            float wv[8] = {w0.x, w0.y, w0.z, w0.w, w1.x, w1.y, w1.z, w1.w};
#pragma unroll
            for (int j = 0; j < 8; j++) {
                acc[0][j] = fmaf(a0, wv[j], acc[0][j]);
                acc[1][j] = fmaf(a1, wv[j], acc[1][j]);
                acc[2][j] = fmaf(a2, wv[j], acc[2][j]);
                acc[3][j] = fmaf(a3, wv[j], acc[3][j]);
            }
        }
        __syncthreads();
    }

#pragma unroll
    for (int r = 0; r < 4; r++) {
        int row = row0 + tr + r;
        if (row < nrows) {
            float4* o = (float4*)(Y + (size_t)row * 128 + tc);
            o[0] = make_float4(acc[r][0], acc[r][1], acc[r][2], acc[r][3]);
            o[1] = make_float4(acc[r][4], acc[r][5], acc[r][6], acc[r][7]);
        }
    }
}

// ---- fused aggregate: bufB[d] = prelu(dinv2*bufA[d] + sum norm*bufA[s] + bias) ----
// Warp per dst node; lane owns one float4 (4 features).
__global__ void k_aggregate(const float* __restrict__ bias,
                            const float* __restrict__ aP, int n, int do_prelu)
{
    int gw   = (blockIdx.x * blockDim.x + threadIdx.x) >> 5;
    int lane = threadIdx.x & 31;
    if (gw >= n) return;

    int   start = g_rowstart[gw];
    int   cnt   = g_deg[gw] - 1;
    float dv    = g_dinv[gw];
    const float* A = g_bufA;

    float4 acc = *((const float4*)(A + (size_t)gw * 128) + lane);
    float  sc  = dv * dv;
    acc.x *= sc; acc.y *= sc; acc.z *= sc; acc.w *= sc;

    if (cnt > 0) {
        float2 e0 = g_edge[start];
        int    s0 = __float_as_int(e0.x);
        float4 v0 = *((const float4*)(A + (size_t)s0 * 128) + lane);
        for (int k = 1; k < cnt; k++) {
            float2 e1 = g_edge[start + k];          // prefetch next edge
            int    s1 = __float_as_int(e1.x);
            float4 v1 = *((const float4*)(A + (size_t)s1 * 128) + lane);
            acc.x = fmaf(e0.y, v0.x, acc.x);
            acc.y = fmaf(e0.y, v0.y, acc.y);
            acc.z = fmaf(e0.y, v0.z, acc.z);
            acc.w = fmaf(e0.y, v0.w, acc.w);
            e0 = e1; v0 = v1;
        }
        acc.x = fmaf(e0.y, v0.x, acc.x);
        acc.y = fmaf(e0.y, v0.y, acc.y);
        acc.z = fmaf(e0.y, v0.z, acc.z);
        acc.w = fmaf(e0.y, v0.w, acc.w);
    }

    float4 b = *((const float4*)bias + lane);
    acc.x += b.x; acc.y += b.y; acc.z += b.z; acc.w += b.w;

    if (do_prelu) {
        float al = aP[0];
        acc.x = acc.x > 0.f ? acc.x : al * acc.x;
        acc.y = acc.y > 0.f ? acc.y : al * acc.y;
        acc.z = acc.z > 0.f ? acc.z : al * acc.z;
        acc.w = acc.w > 0.f ? acc.w : al * acc.w;
    }
    *((float4*)(g_bufB + (size_t)gw * 128) + lane) = acc;
}

// ---------------- pooling ----------------
__global__ void k_pool_init(const int* __restrict__ batch, int n) {
    int t = threadIdx.x;                       // 1 block, 128 threads
    for (int i = t; i < G * F; i += blockDim.x) g_gsum[i] = 0.f;
    if (t < G) {
        int lo, hi;
        {
            int a = 0, b = n;
            while (a < b) { int m = (a + b) >> 1; if (batch[m] < t) a = m + 1; else b = m; }
            lo = a;
        }
        {
            int a = 0, b = n;
            while (a < b) { int m = (a + b) >> 1; if (batch[m] < t + 1) a = m + 1; else b = m; }
            hi = a;
        }
        g_gcnt[t] = hi - lo;
    }
}

// 128 threads per block (one per feature); each block handles 256 nodes.
__global__ void k_pool_sum(const int* __restrict__ batch, int n) {
    int f  = threadIdx.x;                      // 0..127
    int n0 = blockIdx.x * 256;
    int n1 = min(n0 + 256, n);
    int gc = -1;
    float acc = 0.f;
    const float* H = g_bufB;
    for (int nn = n0; nn < n1; nn++) {
        int g = clampi(batch[nn], 0, G - 1);
        if (g != gc) {
            if (gc >= 0) atomicAdd(&g_gsum[gc * F + f], acc);
            acc = 0.f;
            gc = g;
        }
        acc += H[(size_t)nn * F + f];
    }
    if (gc >= 0) atomicAdd(&g_gsum[gc * F + f], acc);
}

__global__ void k_head(const float* __restrict__ linW, const float* __restrict__ linb,
                       float* __restrict__ out) {
    int t = blockIdx.x * blockDim.x + threadIdx.x;     // 640 outputs
    if (t >= G * OUTD) return;
    int g = t / OUTD;
    int o = t % OUTD;
    float c   = fmaxf((float)g_gcnt[g], 1.f);
    float inv = 1.f / c;
    float acc = 0.f;
#pragma unroll 8
    for (int h = 0; h < F; h++)
        acc = fmaf(g_gsum[g * F + h], linW[h * OUTD + o], acc);
    out[t] = acc * inv + linb[o];
}

// ---------------- launch ----------------
extern "C" void kernel_launch(void* const* d_in, const int* in_sizes, int n_in,
                              void* d_out, int out_size)
{
    // Resolve inputs BY SIZE (ordering-proof). Same-shaped tensors keep order.
    int iX = 0, iE = 0, iB = 0, iLW = 0, iLb = 0;
    int iW[3] = {0, 0, 0}, ib[3] = {0, 0, 0}, ia[2] = {0, 0};
    int nW = 0, nb = 0, na = 0;
    for (int i = 0; i < n_in; i++) {
        int s = in_sizes[i];
        if      (s == NMAX * F)   iX = i;
        else if (s == 2 * EMAX)   iE = i;
        else if (s == NMAX)       iB = i;
        else if (s == F * F)      { if (nW < 3) iW[nW++] = i; }
        else if (s == F)          { if (nb < 3) ib[nb++] = i; }
        else if (s == 1)          { if (na < 2) ia[na++] = i; }
        else if (s == F * OUTD)   iLW = i;
        else if (s == OUTD)       iLb = i;
    }

    const float* x    = (const float*)d_in[iX];
    const int*   ei   = (const int*)d_in[iE];    // int32 (JAX x64 disabled)
    const int*   bat  = (const int*)d_in[iB];
    const float* W0   = (const float*)d_in[iW[0]];
    const float* b0   = (const float*)d_in[ib[0]];
    const float* a0   = (const float*)d_in[ia[0]];
    const float* W1   = (const float*)d_in[iW[1]];
    const float* b1   = (const float*)d_in[ib[1]];
    const float* a1   = (const float*)d_in[ia[1]];
    const float* W2   = (const float*)d_in[iW[2]];
    const float* b2   = (const float*)d_in[ib[2]];
    const float* linW = (const float*)d_in[iLW];
    const float* linb = (const float*)d_in[iLb];
    float*       out  = (float*)d_out;

    int n = in_sizes[iX] / F;       // 100000
    int e = in_sizes[iE] / 2;       // 1600000
    const int* src = ei;
    const int* dst = ei + e;

    // ---- precompute: degrees, dinv, CSR ----
    k_deg_init <<<(n + 255) / 256, 256>>>(n);
    k_deg_count<<<(e + 255) / 256, 256>>>(dst, e, n);
    k_dinv     <<<(n + 255) / 256, 256>>>(n);
    int nscan = (n + 1023) / 1024;                  // 98
    k_scan1<<<nscan, 1024>>>(n);
    k_scan2<<<1, 128>>>(nscan);
    k_scan3<<<(n + 255) / 256, 256>>>(n);
    k_csr_fill<<<(e + 255) / 256, 256>>>(src, dst, e, n);

    int gemm_blocks = (n + 63) / 64;
    int agg_blocks  = (n * 32 + 255) / 256;         // warp per node

    // ---- layer 1 ----
    k_gemm128  <<<gemm_blocks, 256>>>(x, 1, W0, n);
    k_aggregate<<<agg_blocks, 256>>>(b0, a0, n, 1);
    // ---- layer 2 ----
    k_gemm128  <<<gemm_blocks, 256>>>(nullptr, 0, W1, n);
    k_aggregate<<<agg_blocks, 256>>>(b1, a1, n, 1);
    // ---- layer 3 (no PReLU) ----
    k_gemm128  <<<gemm_blocks, 256>>>(nullptr, 0, W2, n);
    k_aggregate<<<agg_blocks, 256>>>(b2, nullptr, n, 0);

    // ---- pool + head ----
    k_pool_init<<<1, 128>>>(bat, n);
    k_pool_sum<<<(n + 255) / 256, 128>>>(bat, n);
    k_head<<<3, 256>>>(linW, linb, out);
}

// round 7
// speedup vs baseline: 1.6822x; 1.1713x over previous
#include <cuda_runtime.h>
#include <cuda_bf16.h>
#include <math.h>
#include <stdint.h>

// Problem constants (fixed by the dataset)
#define NMAX 100000
#define EMAX 1600000
#define F    128
#define G    64
#define OUTD 10

// ---------------- device scratch (static, no allocation) ----------------
__device__ float  g_bufA[(size_t)NMAX * F];  // GEMM output h = x @ W
__device__ float  g_bufB[(size_t)NMAX * F];  // aggregation output / next layer input
__device__ float  g_dinv[NMAX];
__device__ int    g_deg[NMAX];               // degree incl. self loop
__device__ int    g_scan[NMAX];              // per-block inclusive scan of (deg-1)
__device__ int    g_bsum[128];               // block sums -> exclusive offsets
__device__ int    g_rowstart[NMAX];          // CSR row start (real edges only)
__device__ int    g_pos[NMAX];               // fill cursor
__device__ float2 g_edge[EMAX];              // packed (src as int bits, norm)
__device__ float  g_gsum[G * F];
__device__ int    g_gcnt[G];

__device__ __forceinline__ int clampi(int v, int lo, int hi) {
    return v < lo ? lo : (v > hi ? hi : v);
}

__device__ __forceinline__ uint32_t f2tf32(float x) {
    uint32_t r;
    asm("cvt.rna.tf32.f32 %0, %1;" : "=r"(r) : "f"(x));
    return r;
}

__device__ __forceinline__ void mma_tf32(float* c, const uint32_t* a,
                                         uint32_t b0, uint32_t b1) {
    asm volatile(
        "mma.sync.aligned.m16n8k8.row.col.f32.tf32.tf32.f32 "
        "{%0,%1,%2,%3},{%4,%5,%6,%7},{%8,%9},{%0,%1,%2,%3};"
        : "+f"(c[0]), "+f"(c[1]), "+f"(c[2]), "+f"(c[3])
        : "r"(a[0]), "r"(a[1]), "r"(a[2]), "r"(a[3]), "r"(b0), "r"(b1));
}

// ---------------- degree / dinv ----------------
__global__ void k_deg_init(int n) {
    int i = blockIdx.x * blockDim.x + threadIdx.x;
    if (i < n) g_deg[i] = 1;            // self loop contributes 1
}

__global__ void k_deg_count(const int* __restrict__ dst, int e, int n) {
    int i = blockIdx.x * blockDim.x + threadIdx.x;
    if (i < e) atomicAdd(&g_deg[clampi(dst[i], 0, n - 1)], 1);
}

__global__ void k_dinv(int n) {
    int i = blockIdx.x * blockDim.x + threadIdx.x;
    if (i < n) g_dinv[i] = rsqrtf((float)g_deg[i]);
}

// ---------------- CSR build: scan of (deg-1), then slot fill ----------------
__global__ void k_scan1(int n) {                 // 1024 threads/block
    __shared__ int sh[1024];
    int gid = blockIdx.x * 1024 + threadIdx.x;
    int v = (gid < n) ? (g_deg[gid] - 1) : 0;
    sh[threadIdx.x] = v;
    __syncthreads();
    for (int off = 1; off < 1024; off <<= 1) {   // Hillis-Steele inclusive
        int t = (threadIdx.x >= off) ? sh[threadIdx.x - off] : 0;
        __syncthreads();
        sh[threadIdx.x] += t;
        __syncthreads();
    }
    if (gid < n) g_scan[gid] = sh[threadIdx.x];
    if (threadIdx.x == 1023) g_bsum[blockIdx.x] = sh[1023];
}

__global__ void k_scan2(int nb) {                // 1 block, 128 threads
    __shared__ int sh[128];
    int t = threadIdx.x;
    sh[t] = (t < nb) ? g_bsum[t] : 0;
    __syncthreads();
    if (t == 0) {
        int acc = 0;
        for (int i = 0; i < nb; i++) { int v = sh[i]; sh[i] = acc; acc += v; }
    }
    __syncthreads();
    if (t < nb) g_bsum[t] = sh[t];
}

__global__ void k_scan3(int n) {
    int gid = blockIdx.x * blockDim.x + threadIdx.x;
    if (gid >= n) return;
    int cnt   = g_deg[gid] - 1;
    int start = g_scan[gid] - cnt + g_bsum[gid >> 10];   // exclusive start
    g_rowstart[gid] = start;
    g_pos[gid]      = start;
}

__global__ void k_csr_fill(const int* __restrict__ src, const int* __restrict__ dst,
                           int e, int n) {
    int i = blockIdx.x * blockDim.x + threadIdx.x;
    if (i >= e) return;
    int s = clampi(src[i], 0, n - 1);
    int d = clampi(dst[i], 0, n - 1);
    int slot = atomicAdd(&g_pos[d], 1);
    g_edge[slot] = make_float2(__int_as_float(s), g_dinv[s] * g_dinv[d]);
}

// ---------------- TF32 tensor-core GEMM (3xTF32 split, ~fp32 accuracy) ---------
// g_bufA[n x 128] = X[n x 128] @ W[128 x 128]
// Block: 256 threads (8 warps), tile 128 rows x 128 cols; warp tile 32x64.
// smem tiles k-major with stride 136 -> conflict-free fill + fragment loads.
#define SAS 136
__global__ __launch_bounds__(256) void k_gemm_tf32(
    const float* __restrict__ Xext, int use_ext,
    const float* __restrict__ W, int nrows)
{
    const float* X = use_ext ? Xext : (const float*)g_bufB;
    float*       Y = g_bufA;

    __shared__ uint32_t sAh[16 * SAS];   // A^T hi : [k][m]
    __shared__ uint32_t sAl[16 * SAS];   // A^T lo
    __shared__ uint32_t sBh[16 * SAS];   // W hi   : [k][n]
    __shared__ uint32_t sBl[16 * SAS];   // W lo

    int tid  = threadIdx.x;
    int row0 = blockIdx.x * 128;
    int lane = tid & 31;
    int wid  = tid >> 5;
    int g    = lane >> 2;          // 0..7
    int t    = lane & 3;           // 0..3
    int wm   = (wid & 3) * 32;     // warp m offset: 0,32,64,96
    int wn   = (wid >> 2) * 64;    // warp n offset: 0,64

    float acc[2][8][4];
#pragma unroll
    for (int mi = 0; mi < 2; mi++)
#pragma unroll
        for (int ni = 0; ni < 8; ni++)
#pragma unroll
            for (int q = 0; q < 4; q++) acc[mi][ni][q] = 0.f;

    for (int kt = 0; kt < 128; kt += 16) {
        // ---- fill A^T tile: sA[k][m] = X[row0+m][kt+k], split hi/lo ----
#pragma unroll
        for (int h = 0; h < 2; h++) {
            int f  = tid + h * 256;                 // 0..511 float4 slots
            int c4 = (f >> 5) & 3;                  // k group (0..3)
            int r  = (f & 31) + ((f >> 7) << 5);    // m row (0..127)
            int row = row0 + r;
            float4 v = make_float4(0.f, 0.f, 0.f, 0.f);
            if (row < nrows) v = *(const float4*)(X + (size_t)row * 128 + kt + c4 * 4);
            float xs[4] = {v.x, v.y, v.z, v.w};
#pragma unroll
            for (int i = 0; i < 4; i++) {
                uint32_t hi = f2tf32(xs[i]);
                uint32_t lo = f2tf32(xs[i] - __uint_as_float(hi));
                sAh[(c4 * 4 + i) * SAS + r] = hi;
                sAl[(c4 * 4 + i) * SAS + r] = lo;
            }
        }
        // ---- fill W tile: sB[k][n] = W[kt+k][n], split hi/lo ----
#pragma unroll
        for (int h = 0; h < 2; h++) {
            int f = tid + h * 256;                  // 0..511
            int k = f >> 5;                         // 0..15
            int c = (f & 31) * 4;                   // 0..124
            float4 v = *(const float4*)(W + (size_t)(kt + k) * 128 + c);
            float xs[4] = {v.x, v.y, v.z, v.w};
#pragma unroll
            for (int i = 0; i < 4; i++) {
                uint32_t hi = f2tf32(xs[i]);
                uint32_t lo = f2tf32(xs[i] - __uint_as_float(hi));
                sBh[k * SAS + c + i] = hi;
                sBl[k * SAS + c + i] = lo;
            }
        }
        __syncthreads();

#pragma unroll
        for (int k0 = 0; k0 < 16; k0 += 8) {
            uint32_t ah[2][4], al[2][4];
#pragma unroll
            for (int mi = 0; mi < 2; mi++) {
                int m = wm + mi * 16;
                ah[mi][0] = sAh[(k0 + t) * SAS + m + g];
                ah[mi][1] = sAh[(k0 + t) * SAS + m + g + 8];
                ah[mi][2] = sAh[(k0 + t + 4) * SAS + m + g];
                ah[mi][3] = sAh[(k0 + t + 4) * SAS + m + g + 8];
                al[mi][0] = sAl[(k0 + t) * SAS + m + g];
                al[mi][1] = sAl[(k0 + t) * SAS + m + g + 8];
                al[mi][2] = sAl[(k0 + t + 4) * SAS + m + g];
                al[mi][3] = sAl[(k0 + t + 4) * SAS + m + g + 8];
            }
#pragma unroll
            for (int ni = 0; ni < 8; ni++) {
                int n = wn + ni * 8 + g;
                uint32_t bh0 = sBh[(k0 + t) * SAS + n];
                uint32_t bh1 = sBh[(k0 + t + 4) * SAS + n];
                uint32_t bl0 = sBl[(k0 + t) * SAS + n];
                uint32_t bl1 = sBl[(k0 + t + 4) * SAS + n];
#pragma unroll
                for (int mi = 0; mi < 2; mi++) {
                    mma_tf32(acc[mi][ni], ah[mi], bh0, bh1);   // hi*hi
                    mma_tf32(acc[mi][ni], al[mi], bh0, bh1);   // lo*hi
                    mma_tf32(acc[mi][ni], ah[mi], bl0, bl1);   // hi*lo
                }
            }
        }
        __syncthreads();
    }

    // ---- write C fragments: c0:(g,2t) c1:(g,2t+1) c2:(g+8,2t) c3:(g+8,2t+1) ----
#pragma unroll
    for (int mi = 0; mi < 2; mi++) {
#pragma unroll
        for (int ni = 0; ni < 8; ni++) {
            int col = wn + ni * 8 + t * 2;
            int r0  = row0 + wm + mi * 16 + g;
            int r1  = r0 + 8;
            if (r0 < nrows)
                *(float2*)(Y + (size_t)r0 * 128 + col) = make_float2(acc[mi][ni][0], acc[mi][ni][1]);
            if (r1 < nrows)
                *(float2*)(Y + (size_t)r1 * 128 + col) = make_float2(acc[mi][ni][2], acc[mi][ni][3]);
        }
    }
}

// ---- fused aggregate: bufB[d] = prelu(dinv2*bufA[d] + sum norm*bufA[s] + bias) ----
// Warp per dst node; lane owns one float4 (4 features).
__global__ void k_aggregate(const float* __restrict__ bias,
                            const float* __restrict__ aP, int n, int do_prelu)
{
    int gw   = (blockIdx.x * blockDim.x + threadIdx.x) >> 5;
    int lane = threadIdx.x & 31;
    if (gw >= n) return;

    int   start = g_rowstart[gw];
    int   cnt   = g_deg[gw] - 1;
    float dv    = g_dinv[gw];
    const float* A = g_bufA;

    float4 acc = *((const float4*)(A + (size_t)gw * 128) + lane);
    float  sc  = dv * dv;
    acc.x *= sc; acc.y *= sc; acc.z *= sc; acc.w *= sc;

    if (cnt > 0) {
        float2 e0 = g_edge[start];
        int    s0 = __float_as_int(e0.x);
        float4 v0 = *((const float4*)(A + (size_t)s0 * 128) + lane);
        for (int k = 1; k < cnt; k++) {
            float2 e1 = g_edge[start + k];          // prefetch next edge
            int    s1 = __float_as_int(e1.x);
            float4 v1 = *((const float4*)(A + (size_t)s1 * 128) + lane);
            acc.x = fmaf(e0.y, v0.x, acc.x);
            acc.y = fmaf(e0.y, v0.y, acc.y);
            acc.z = fmaf(e0.y, v0.z, acc.z);
            acc.w = fmaf(e0.y, v0.w, acc.w);
            e0 = e1; v0 = v1;
        }
        acc.x = fmaf(e0.y, v0.x, acc.x);
        acc.y = fmaf(e0.y, v0.y, acc.y);
        acc.z = fmaf(e0.y, v0.z, acc.z);
        acc.w = fmaf(e0.y, v0.w, acc.w);
    }

    float4 b = *((const float4*)bias + lane);
    acc.x += b.x; acc.y += b.y; acc.z += b.z; acc.w += b.w;

    if (do_prelu) {
        float al = aP[0];
        acc.x = acc.x > 0.f ? acc.x : al * acc.x;
        acc.y = acc.y > 0.f ? acc.y : al * acc.y;
        acc.z = acc.z > 0.f ? acc.z : al * acc.z;
        acc.w = acc.w > 0.f ? acc.w : al * acc.w;
    }
    *((float4*)(g_bufB + (size_t)gw * 128) + lane) = acc;
}

// ---------------- pooling ----------------
__global__ void k_pool_init(const int* __restrict__ batch, int n) {
    int t = threadIdx.x;                       // 1 block, 128 threads
    for (int i = t; i < G * F; i += blockDim.x) g_gsum[i] = 0.f;
    if (t < G) {
        int lo, hi;
        {
            int a = 0, b = n;
            while (a < b) { int m = (a + b) >> 1; if (batch[m] < t) a = m + 1; else b = m; }
            lo = a;
        }
        {
            int a = 0, b = n;
            while (a < b) { int m = (a + b) >> 1; if (batch[m] < t + 1) a = m + 1; else b = m; }
            hi = a;
        }
        g_gcnt[t] = hi - lo;
    }
}

// 128 threads per block (one per feature); each block handles 256 nodes.
__global__ void k_pool_sum(const int* __restrict__ batch, int n) {
    int f  = threadIdx.x;                      // 0..127
    int n0 = blockIdx.x * 256;
    int n1 = min(n0 + 256, n);
    int gc = -1;
    float acc = 0.f;
    const float* H = g_bufB;
    for (int nn = n0; nn < n1; nn++) {
        int g = clampi(batch[nn], 0, G - 1);
        if (g != gc) {
            if (gc >= 0) atomicAdd(&g_gsum[gc * F + f], acc);
            acc = 0.f;
            gc = g;
        }
        acc += H[(size_t)nn * F + f];
    }
    if (gc >= 0) atomicAdd(&g_gsum[gc * F + f], acc);
}

__global__ void k_head(const float* __restrict__ linW, const float* __restrict__ linb,
                       float* __restrict__ out) {
    int t = blockIdx.x * blockDim.x + threadIdx.x;     // 640 outputs
    if (t >= G * OUTD) return;
    int g = t / OUTD;
    int o = t % OUTD;
    float c   = fmaxf((float)g_gcnt[g], 1.f);
    float inv = 1.f / c;
    float acc = 0.f;
#pragma unroll 8
    for (int h = 0; h < F; h++)
        acc = fmaf(g_gsum[g * F + h], linW[h * OUTD + o], acc);
    out[t] = acc * inv + linb[o];
}

// ---------------- launch ----------------
extern "C" void kernel_launch(void* const* d_in, const int* in_sizes, int n_in,
                              void* d_out, int out_size)
{
    // Resolve inputs BY SIZE (ordering-proof). Same-shaped tensors keep order.
    int iX = 0, iE = 0, iB = 0, iLW = 0, iLb = 0;
    int iW[3] = {0, 0, 0}, ib[3] = {0, 0, 0}, ia[2] = {0, 0};
    int nW = 0, nb = 0, na = 0;
    for (int i = 0; i < n_in; i++) {
        int s = in_sizes[i];
        if      (s == NMAX * F)   iX = i;
        else if (s == 2 * EMAX)   iE = i;
        else if (s == NMAX)       iB = i;
        else if (s == F * F)      { if (nW < 3) iW[nW++] = i; }
        else if (s == F)          { if (nb < 3) ib[nb++] = i; }
        else if (s == 1)          { if (na < 2) ia[na++] = i; }
        else if (s == F * OUTD)   iLW = i;
        else if (s == OUTD)       iLb = i;
    }

    const float* x    = (const float*)d_in[iX];
    const int*   ei   = (const int*)d_in[iE];    // int32 (JAX x64 disabled)
    const int*   bat  = (const int*)d_in[iB];
    const float* W0   = (const float*)d_in[iW[0]];
    const float* b0   = (const float*)d_in[ib[0]];
    const float* a0   = (const float*)d_in[ia[0]];
    const float* W1   = (const float*)d_in[iW[1]];
    const float* b1   = (const float*)d_in[ib[1]];
    const float* a1   = (const float*)d_in[ia[1]];
    const float* W2   = (const float*)d_in[iW[2]];
    const float* b2   = (const float*)d_in[ib[2]];
    const float* linW = (const float*)d_in[iLW];
    const float* linb = (const float*)d_in[iLb];
    float*       out  = (float*)d_out;

    int n = in_sizes[iX] / F;       // 100000
    int e = in_sizes[iE] / 2;       // 1600000
    const int* src = ei;
    const int* dst = ei + e;

    // ---- precompute: degrees, dinv, CSR ----
    k_deg_init <<<(n + 255) / 256, 256>>>(n);
    k_deg_count<<<(e + 255) / 256, 256>>>(dst, e, n);
    k_dinv     <<<(n + 255) / 256, 256>>>(n);
    int nscan = (n + 1023) / 1024;                  // 98
    k_scan1<<<nscan, 1024>>>(n);
    k_scan2<<<1, 128>>>(nscan);
    k_scan3<<<(n + 255) / 256, 256>>>(n);
    k_csr_fill<<<(e + 255) / 256, 256>>>(src, dst, e, n);

    int gemm_blocks = (n + 127) / 128;
    int agg_blocks  = (n * 32 + 255) / 256;         // warp per node

    // ---- layer 1 ----
    k_gemm_tf32<<<gemm_blocks, 256>>>(x, 1, W0, n);
    k_aggregate<<<agg_blocks, 256>>>(b0, a0, n, 1);
    // ---- layer 2 ----
    k_gemm_tf32<<<gemm_blocks, 256>>>(nullptr, 0, W1, n);
    k_aggregate<<<agg_blocks, 256>>>(b1, a1, n, 1);
    // ---- layer 3 (no PReLU) ----
    k_gemm_tf32<<<gemm_blocks, 256>>>(nullptr, 0, W2, n);
    k_aggregate<<<agg_blocks, 256>>>(b2, nullptr, n, 0);

    // ---- pool + head ----
    k_pool_init<<<1, 128>>>(bat, n);
    k_pool_sum<<<(n + 255) / 256, 128>>>(bat, n);
    k_head<<<3, 256>>>(linW, linb, out);
}

// round 8
// speedup vs baseline: 1.8091x; 1.0754x over previous
#include <cuda_runtime.h>
#include <cuda_bf16.h>
#include <cuda_fp16.h>
#include <math.h>
#include <stdint.h>

// Problem constants (fixed by the dataset)
#define NMAX 100000
#define EMAX 1600000
#define F    128
#define G    64
#define OUTD 10

// ---------------- device scratch (static, no allocation) ----------------
__device__ float   g_bufA[(size_t)NMAX * F];   // GEMM output h = x @ W (fp32)
__device__ __half2 g_bufA16[(size_t)NMAX * 64];// GEMM output h (fp16, for gathers)
__device__ float   g_bufB[(size_t)NMAX * F];   // aggregation output / next layer input
__device__ float   g_dinv[NMAX];
__device__ int     g_deg[NMAX];                // degree incl. self loop
__device__ int     g_scan[NMAX];               // per-block inclusive scan of (deg-1)
__device__ int     g_bsum[128];                // block sums -> exclusive offsets
__device__ int     g_rowstart[NMAX];           // CSR row start (real edges only)
__device__ int     g_pos[NMAX];                // fill cursor
__device__ float2  g_edge[EMAX];               // packed (src as int bits, norm)
__device__ float   g_gsum[G * F];
__device__ int     g_gcnt[G];

__device__ __forceinline__ int clampi(int v, int lo, int hi) {
    return v < lo ? lo : (v > hi ? hi : v);
}

__device__ __forceinline__ uint32_t f2tf32(float x) {
    uint32_t r;
    asm("cvt.rna.tf32.f32 %0, %1;" : "=r"(r) : "f"(x));
    return r;
}

__device__ __forceinline__ void mma_tf32(float* c, const uint32_t* a,
                                         uint32_t b0, uint32_t b1) {
    asm volatile(
        "mma.sync.aligned.m16n8k8.row.col.f32.tf32.tf32.f32 "
        "{%0,%1,%2,%3},{%4,%5,%6,%7},{%8,%9},{%0,%1,%2,%3};"
        : "+f"(c[0]), "+f"(c[1]), "+f"(c[2]), "+f"(c[3])
        : "r"(a[0]), "r"(a[1]), "r"(a[2]), "r"(a[3]), "r"(b0), "r"(b1));
}

// ---------------- degree / dinv ----------------
__global__ void k_deg_init(int n) {
    int i = blockIdx.x * blockDim.x + threadIdx.x;
    if (i < n) g_deg[i] = 1;            // self loop contributes 1
}

__global__ void k_deg_count(const int* __restrict__ dst, int e, int n) {
    int i = blockIdx.x * blockDim.x + threadIdx.x;
    if (i < e) atomicAdd(&g_deg[clampi(dst[i], 0, n - 1)], 1);
}

__global__ void k_dinv(int n) {
    int i = blockIdx.x * blockDim.x + threadIdx.x;
    if (i < n) g_dinv[i] = rsqrtf((float)g_deg[i]);
}

// ---------------- CSR build: scan of (deg-1), then slot fill ----------------
__global__ void k_scan1(int n) {                 // 1024 threads/block
    __shared__ int sh[1024];
    int gid = blockIdx.x * 1024 + threadIdx.x;
    int v = (gid < n) ? (g_deg[gid] - 1) : 0;
    sh[threadIdx.x] = v;
    __syncthreads();
    for (int off = 1; off < 1024; off <<= 1) {   // Hillis-Steele inclusive
        int t = (threadIdx.x >= off) ? sh[threadIdx.x - off] : 0;
        __syncthreads();
        sh[threadIdx.x] += t;
        __syncthreads();
    }
    if (gid < n) g_scan[gid] = sh[threadIdx.x];
    if (threadIdx.x == 1023) g_bsum[blockIdx.x] = sh[1023];
}

__global__ void k_scan2(int nb) {                // 1 block, 128 threads
    __shared__ int sh[128];
    int t = threadIdx.x;
    sh[t] = (t < nb) ? g_bsum[t] : 0;
    __syncthreads();
    if (t == 0) {
        int acc = 0;
        for (int i = 0; i < nb; i++) { int v = sh[i]; sh[i] = acc; acc += v; }
    }
    __syncthreads();
    if (t < nb) g_bsum[t] = sh[t];
}

__global__ void k_scan3(int n) {
    int gid = blockIdx.x * blockDim.x + threadIdx.x;
    if (gid >= n) return;
    int cnt   = g_deg[gid] - 1;
    int start = g_scan[gid] - cnt + g_bsum[gid >> 10];   // exclusive start
    g_rowstart[gid] = start;
    g_pos[gid]      = start;
}

__global__ void k_csr_fill(const int* __restrict__ src, const int* __restrict__ dst,
                           int e, int n) {
    int i = blockIdx.x * blockDim.x + threadIdx.x;
    if (i >= e) return;
    int s = clampi(src[i], 0, n - 1);
    int d = clampi(dst[i], 0, n - 1);
    int slot = atomicAdd(&g_pos[d], 1);
    g_edge[slot] = make_float2(__int_as_float(s), g_dinv[s] * g_dinv[d]);
}

// ---------------- TF32 tensor-core GEMM (3xTF32 split, ~fp32 accuracy) ---------
// g_bufA[n x 128] = X[n x 128] @ W[128 x 128]; also writes fp16 copy g_bufA16.
// Block: 256 threads (8 warps), tile 128 rows x 128 cols; warp tile 32x64.
#define SAS 136
__global__ __launch_bounds__(256) void k_gemm_tf32(
    const float* __restrict__ Xext, int use_ext,
    const float* __restrict__ W, int nrows)
{
    const float* X = use_ext ? Xext : (const float*)g_bufB;
    float*       Y = g_bufA;

    __shared__ uint32_t sAh[16 * SAS];   // A^T hi : [k][m]
    __shared__ uint32_t sAl[16 * SAS];   // A^T lo
    __shared__ uint32_t sBh[16 * SAS];   // W hi   : [k][n]
    __shared__ uint32_t sBl[16 * SAS];   // W lo

    int tid  = threadIdx.x;
    int row0 = blockIdx.x * 128;
    int lane = tid & 31;
    int wid  = tid >> 5;
    int g    = lane >> 2;          // 0..7
    int t    = lane & 3;           // 0..3
    int wm   = (wid & 3) * 32;     // warp m offset: 0,32,64,96
    int wn   = (wid >> 2) * 64;    // warp n offset: 0,64

    float acc[2][8][4];
#pragma unroll
    for (int mi = 0; mi < 2; mi++)
#pragma unroll
        for (int ni = 0; ni < 8; ni++)
#pragma unroll
            for (int q = 0; q < 4; q++) acc[mi][ni][q] = 0.f;

    for (int kt = 0; kt < 128; kt += 16) {
        // ---- fill A^T tile: sA[k][m] = X[row0+m][kt+k], split hi/lo ----
#pragma unroll
        for (int h = 0; h < 2; h++) {
            int f  = tid + h * 256;                 // 0..511 float4 slots
            int c4 = (f >> 5) & 3;                  // k group (0..3)
            int r  = (f & 31) + ((f >> 7) << 5);    // m row (0..127)
            int row = row0 + r;
            float4 v = make_float4(0.f, 0.f, 0.f, 0.f);
            if (row < nrows) v = *(const float4*)(X + (size_t)row * 128 + kt + c4 * 4);
            float xs[4] = {v.x, v.y, v.z, v.w};
#pragma unroll
            for (int i = 0; i < 4; i++) {
                uint32_t hi = f2tf32(xs[i]);
                uint32_t lo = f2tf32(xs[i] - __uint_as_float(hi));
                sAh[(c4 * 4 + i) * SAS + r] = hi;
                sAl[(c4 * 4 + i) * SAS + r] = lo;
            }
        }
        // ---- fill W tile: sB[k][n] = W[kt+k][n], split hi/lo ----
#pragma unroll
        for (int h = 0; h < 2; h++) {
            int f = tid + h * 256;                  // 0..511
            int k = f >> 5;                         // 0..15
            int c = (f & 31) * 4;                   // 0..124
            float4 v = *(const float4*)(W + (size_t)(kt + k) * 128 + c);
            float xs[4] = {v.x, v.y, v.z, v.w};
#pragma unroll
            for (int i = 0; i < 4; i++) {
                uint32_t hi = f2tf32(xs[i]);
                uint32_t lo = f2tf32(xs[i] - __uint_as_float(hi));
                sBh[k * SAS + c + i] = hi;
                sBl[k * SAS + c + i] = lo;
            }
        }
        __syncthreads();

#pragma unroll
        for (int k0 = 0; k0 < 16; k0 += 8) {
            uint32_t ah[2][4], al[2][4];
#pragma unroll
            for (int mi = 0; mi < 2; mi++) {
                int m = wm + mi * 16;
                ah[mi][0] = sAh[(k0 + t) * SAS + m + g];
                ah[mi][1] = sAh[(k0 + t) * SAS + m + g + 8];
                ah[mi][2] = sAh[(k0 + t + 4) * SAS + m + g];
                ah[mi][3] = sAh[(k0 + t + 4) * SAS + m + g + 8];
                al[mi][0] = sAl[(k0 + t) * SAS + m + g];
                al[mi][1] = sAl[(k0 + t) * SAS + m + g + 8];
                al[mi][2] = sAl[(k0 + t + 4) * SAS + m + g];
                al[mi][3] = sAl[(k0 + t + 4) * SAS + m + g + 8];
            }
#pragma unroll
            for (int ni = 0; ni < 8; ni++) {
                int n = wn + ni * 8 + g;
                uint32_t bh0 = sBh[(k0 + t) * SAS + n];
                uint32_t bh1 = sBh[(k0 + t + 4) * SAS + n];
                uint32_t bl0 = sBl[(k0 + t) * SAS + n];
                uint32_t bl1 = sBl[(k0 + t + 4) * SAS + n];
#pragma unroll
                for (int mi = 0; mi < 2; mi++) {
                    mma_tf32(acc[mi][ni], ah[mi], bh0, bh1);   // hi*hi
                    mma_tf32(acc[mi][ni], al[mi], bh0, bh1);   // lo*hi
                    mma_tf32(acc[mi][ni], ah[mi], bl0, bl1);   // hi*lo
                }
            }
        }
        __syncthreads();
    }

    // ---- write C fragments (fp32 + fp16 copy) ----
#pragma unroll
    for (int mi = 0; mi < 2; mi++) {
#pragma unroll
        for (int ni = 0; ni < 8; ni++) {
            int col = wn + ni * 8 + t * 2;          // even
            int r0  = row0 + wm + mi * 16 + g;
            int r1  = r0 + 8;
            float2 v0 = make_float2(acc[mi][ni][0], acc[mi][ni][1]);
            float2 v1 = make_float2(acc[mi][ni][2], acc[mi][ni][3]);
            if (r0 < nrows) {
                *(float2*)(Y + (size_t)r0 * 128 + col) = v0;
                g_bufA16[(size_t)r0 * 64 + (col >> 1)] = __float22half2_rn(v0);
            }
            if (r1 < nrows) {
                *(float2*)(Y + (size_t)r1 * 128 + col) = v1;
                g_bufA16[(size_t)r1 * 64 + (col >> 1)] = __float22half2_rn(v1);
            }
        }
    }
}

// ---- fused aggregate: bufB[d] = prelu(dinv2*bufA[d] + sum norm*h16[s] + bias) ----
// Warp per dst node; lane owns 4 features. Self term fp32, gathers fp16.
__global__ void k_aggregate(const float* __restrict__ bias,
                            const float* __restrict__ aP, int n, int do_prelu)
{
    int gw   = (blockIdx.x * blockDim.x + threadIdx.x) >> 5;
    int lane = threadIdx.x & 31;
    if (gw >= n) return;

    int   start = g_rowstart[gw];
    int   cnt   = g_deg[gw] - 1;
    float dv    = g_dinv[gw];

    float4 acc = *((const float4*)(g_bufA + (size_t)gw * 128) + lane);
    float  sc  = dv * dv;
    acc.x *= sc; acc.y *= sc; acc.z *= sc; acc.w *= sc;

    if (cnt > 0) {
        float2 e0 = g_edge[start];
        int    s0 = __float_as_int(e0.x);
        uint2  h0 = *((const uint2*)(g_bufA16 + (size_t)s0 * 64) + lane);
        for (int k = 1; k < cnt; k++) {
            float2 e1 = g_edge[start + k];          // prefetch next edge
            int    s1 = __float_as_int(e1.x);
            uint2  h1 = *((const uint2*)(g_bufA16 + (size_t)s1 * 64) + lane);
            float2 p0 = __half22float2(*(const __half2*)&h0.x);
            float2 p1 = __half22float2(*(const __half2*)&h0.y);
            acc.x = fmaf(e0.y, p0.x, acc.x);
            acc.y = fmaf(e0.y, p0.y, acc.y);
            acc.z = fmaf(e0.y, p1.x, acc.z);
            acc.w = fmaf(e0.y, p1.y, acc.w);
            e0 = e1; h0 = h1;
        }
        float2 p0 = __half22float2(*(const __half2*)&h0.x);
        float2 p1 = __half22float2(*(const __half2*)&h0.y);
        acc.x = fmaf(e0.y, p0.x, acc.x);
        acc.y = fmaf(e0.y, p0.y, acc.y);
        acc.z = fmaf(e0.y, p1.x, acc.z);
        acc.w = fmaf(e0.y, p1.y, acc.w);
    }

    float4 b = *((const float4*)bias + lane);
    acc.x += b.x; acc.y += b.y; acc.z += b.z; acc.w += b.w;

    if (do_prelu) {
        float al = aP[0];
        acc.x = acc.x > 0.f ? acc.x : al * acc.x;
        acc.y = acc.y > 0.f ? acc.y : al * acc.y;
        acc.z = acc.z > 0.f ? acc.z : al * acc.z;
        acc.w = acc.w > 0.f ? acc.w : al * acc.w;
    }
    *((float4*)(g_bufB + (size_t)gw * 128) + lane) = acc;
}

// ---------------- pooling ----------------
__global__ void k_pool_init(const int* __restrict__ batch, int n) {
    int t = threadIdx.x;                       // 1 block, 128 threads
    for (int i = t; i < G * F; i += blockDim.x) g_gsum[i] = 0.f;
    if (t < G) {
        int lo, hi;
        {
            int a = 0, b = n;
            while (a < b) { int m = (a + b) >> 1; if (batch[m] < t) a = m + 1; else b = m; }
            lo = a;
        }
        {
            int a = 0, b = n;
            while (a < b) { int m = (a + b) >> 1; if (batch[m] < t + 1) a = m + 1; else b = m; }
            hi = a;
        }
        g_gcnt[t] = hi - lo;
    }
}

// 128 threads per block (one per feature); each block handles 256 nodes.
__global__ void k_pool_sum(const int* __restrict__ batch, int n) {
    int f  = threadIdx.x;                      // 0..127
    int n0 = blockIdx.x * 256;
    int n1 = min(n0 + 256, n);
    int gc = -1;
    float acc = 0.f;
    const float* H = g_bufB;
    for (int nn = n0; nn < n1; nn++) {
        int g = clampi(batch[nn], 0, G - 1);
        if (g != gc) {
            if (gc >= 0) atomicAdd(&g_gsum[gc * F + f], acc);
            acc = 0.f;
            gc = g;
        }
        acc += H[(size_t)nn * F + f];
    }
    if (gc >= 0) atomicAdd(&g_gsum[gc * F + f], acc);
}

__global__ void k_head(const float* __restrict__ linW, const float* __restrict__ linb,
                       float* __restrict__ out) {
    int t = blockIdx.x * blockDim.x + threadIdx.x;     // 640 outputs
    if (t >= G * OUTD) return;
    int g = t / OUTD;
    int o = t % OUTD;
    float c   = fmaxf((float)g_gcnt[g], 1.f);
    float inv = 1.f / c;
    float acc = 0.f;
#pragma unroll 8
    for (int h = 0; h < F; h++)
        acc = fmaf(g_gsum[g * F + h], linW[h * OUTD + o], acc);
    out[t] = acc * inv + linb[o];
}

// ---------------- launch ----------------
extern "C" void kernel_launch(void* const* d_in, const int* in_sizes, int n_in,
                              void* d_out, int out_size)
{
    // Resolve inputs BY SIZE (ordering-proof). Same-shaped tensors keep order.
    int iX = 0, iE = 0, iB = 0, iLW = 0, iLb = 0;
    int iW[3] = {0, 0, 0}, ib[3] = {0, 0, 0}, ia[2] = {0, 0};
    int nW = 0, nb = 0, na = 0;
    for (int i = 0; i < n_in; i++) {
        int s = in_sizes[i];
        if      (s == NMAX * F)   iX = i;
        else if (s == 2 * EMAX)   iE = i;
        else if (s == NMAX)       iB = i;
        else if (s == F * F)      { if (nW < 3) iW[nW++] = i; }
        else if (s == F)          { if (nb < 3) ib[nb++] = i; }
        else if (s == 1)          { if (na < 2) ia[na++] = i; }
        else if (s == F * OUTD)   iLW = i;
        else if (s == OUTD)       iLb = i;
    }

    const float* x    = (const float*)d_in[iX];
    const int*   ei   = (const int*)d_in[iE];    // int32 (JAX x64 disabled)
    const int*   bat  = (const int*)d_in[iB];
    const float* W0   = (const float*)d_in[iW[0]];
    const float* b0   = (const float*)d_in[ib[0]];
    const float* a0   = (const float*)d_in[ia[0]];
    const float* W1   = (const float*)d_in[iW[1]];
    const float* b1   = (const float*)d_in[ib[1]];
    const float* a1   = (const float*)d_in[ia[1]];
    const float* W2   = (const float*)d_in[iW[2]];
    const float* b2   = (const float*)d_in[ib[2]];
    const float* linW = (const float*)d_in[iLW];
    const float* linb = (const float*)d_in[iLb];
    float*       out  = (float*)d_out;

    int n = in_sizes[iX] / F;       // 100000
    int e = in_sizes[iE] / 2;       // 1600000
    const int* src = ei;
    const int* dst = ei + e;

    // ---- precompute: degrees, dinv, CSR ----
    k_deg_init <<<(n + 255) / 256, 256>>>(n);
    k_deg_count<<<(e + 255) / 256, 256>>>(dst, e, n);
    k_dinv     <<<(n + 255) / 256, 256>>>(n);
    int nscan = (n + 1023) / 1024;                  // 98
    k_scan1<<<nscan, 1024>>>(n);
    k_scan2<<<1, 128>>>(nscan);
    k_scan3<<<(n + 255) / 256, 256>>>(n);
    k_csr_fill<<<(e + 255) / 256, 256>>>(src, dst, e, n);

    int gemm_blocks = (n + 127) / 128;
    int agg_blocks  = (n * 32 + 255) / 256;         // warp per node

    // ---- layer 1 ----
    k_gemm_tf32<<<gemm_blocks, 256>>>(x, 1, W0, n);
    k_aggregate<<<agg_blocks, 256>>>(b0, a0, n, 1);
    // ---- layer 2 ----
    k_gemm_tf32<<<gemm_blocks, 256>>>(nullptr, 0, W1, n);
    k_aggregate<<<agg_blocks, 256>>>(b1, a1, n, 1);
    // ---- layer 3 (no PReLU) ----
    k_gemm_tf32<<<gemm_blocks, 256>>>(nullptr, 0, W2, n);
    k_aggregate<<<agg_blocks, 256>>>(b2, nullptr, n, 0);

    // ---- pool + head ----
    k_pool_init<<<1, 128>>>(bat, n);
    k_pool_sum<<<(n + 255) / 256, 128>>>(bat, n);
    k_head<<<3, 256>>>(linW, linb, out);
}